// round 2
// baseline (speedup 1.0000x reference)
#include <cuda_runtime.h>
#include <cuda_bf16.h>
#include <cstdint>

#define D_IN   1024
#define D_OUT  128
#define TILE_M 128
#define KC     32
#define NCHUNK (D_IN / KC)

// -------- persistent scratch (no allocations allowed) --------
__device__ __align__(16) __nv_bfloat16 g_Wt[D_OUT * D_IN];  // [n][k] = round(clip(W)*127), exact in bf16
__device__ float g_bq[D_OUT];

// -------- smem layout (dynamic), rows padded to 80B (conflict-free ldmatrix) ----
#define ASTRIDE 80
#define A_BYTES (128 * ASTRIDE)            // 10240
#define STAGE   (3 * A_BYTES)              // A_hi + A_lo + B = 30720
#define AHI(s)  ((s) * STAGE)
#define ALO(s)  (AHI(s) + A_BYTES)
#define BB(s)   (AHI(s) + 2 * A_BYTES)
#define SMEM_TOTAL (2 * STAGE)             // 61440 -> 2 CTAs/SM

// -------- PTX helpers --------
__device__ __forceinline__ uint32_t smem_u32(const void* p) {
    uint32_t a;
    asm("{ .reg .u64 t; cvta.to.shared.u64 t, %1; cvt.u32.u64 %0, t; }" : "=r"(a) : "l"(p));
    return a;
}
#define CP_ASYNC16(dst, src) \
    asm volatile("cp.async.cg.shared.global [%0], [%1], 16;" :: "r"(dst), "l"(src) : "memory")
#define CP_COMMIT()  asm volatile("cp.async.commit_group;" ::: "memory")
#define CP_WAIT0()   asm volatile("cp.async.wait_group 0;" ::: "memory")

__device__ __forceinline__ void ldm_x4(uint32_t& r0, uint32_t& r1, uint32_t& r2, uint32_t& r3,
                                       uint32_t addr) {
    asm volatile("ldmatrix.sync.aligned.m8n8.x4.shared.b16 {%0,%1,%2,%3}, [%4];"
                 : "=r"(r0), "=r"(r1), "=r"(r2), "=r"(r3) : "r"(addr));
}
__device__ __forceinline__ void mma16816(float* c, const uint32_t* a, const uint32_t* b) {
    asm volatile("mma.sync.aligned.m16n8k16.row.col.f32.bf16.bf16.f32 "
                 "{%0,%1,%2,%3}, {%4,%5,%6,%7}, {%8,%9}, {%0,%1,%2,%3};"
                 : "+f"(c[0]), "+f"(c[1]), "+f"(c[2]), "+f"(c[3])
                 : "r"(a[0]), "r"(a[1]), "r"(a[2]), "r"(a[3]), "r"(b[0]), "r"(b[1]));
}
__device__ __forceinline__ uint32_t pack_bf16(__nv_bfloat16 a, __nv_bfloat16 b) {
    __nv_bfloat162 t(a, b);
    return *reinterpret_cast<uint32_t*>(&t);
}

// -------- prep: quantize + transpose W (coalesced both sides), quantize b --------
__global__ void pwb_prep(const float* __restrict__ W, const float* __restrict__ b) {
    __shared__ float t[32][33];
    int tx = threadIdx.x, ty = threadIdx.y;
    int k0 = blockIdx.x * 32, n0 = blockIdx.y * 32;
    float w = W[(size_t)(k0 + ty) * D_OUT + n0 + tx];
    t[ty][tx] = rintf(fminf(fmaxf(w, -1.f), 1.f) * 127.f);   // integer, exact in bf16
    __syncthreads();
    g_Wt[(size_t)(n0 + ty) * D_IN + k0 + tx] = __float2bfloat16(t[tx][ty]);
    if (blockIdx.x == 0 && blockIdx.y == 0) {
        int tid = ty * 32 + tx;
        if (tid < D_OUT)
            g_bq[tid] = rintf(fminf(fmaxf(b[tid], -1.f), 1.f) * 127.f) * (1.0f / 127.0f);
    }
}

// -------- main GEMM: split-bf16 x, exact-bf16 integer W, fp32 accumulate --------
__global__ void __launch_bounds__(256, 2)
pwb_gemm(const float* __restrict__ x, float* __restrict__ out, int Mtotal) {
    extern __shared__ char smem[];
    uint32_t sb = smem_u32(smem);
    int tid = threadIdx.x;
    int m0 = blockIdx.x * TILE_M;

    int l  = tid & 31;
    int w  = tid >> 5;
    int wm = w & 1;          // 2 warp-rows of 64
    int wn = w >> 1;         // 4 warp-cols of 32

    // ---- loader mapping: 2 threads per row, 16 floats each ----
    int r    = tid >> 1;
    int half = tid & 1;
    const float* px = x + (size_t)(m0 + r) * D_IN + half * 16;
    const __nv_bfloat16* pw = reinterpret_cast<const __nv_bfloat16*>(g_Wt)
                              + (size_t)r * D_IN + half * 16;
    uint32_t a_sts = r * ASTRIDE + half * 32;                 // 32B of bf16 per thread
    uint32_t b_dst = r * ASTRIDE + half * 32;

    // ---- ldmatrix lane address bases ----
    uint32_t a_base[4], b_base[2];
    #pragma unroll
    for (int i = 0; i < 4; i++) {
        int arow = wm * 64 + i * 16 + (l & 15);
        a_base[i] = arow * ASTRIDE + (l >> 4) * 16;
    }
    #pragma unroll
    for (int jj = 0; jj < 2; jj++) {
        int brow = wn * 32 + jj * 16 + ((l >> 4) & 1) * 8 + (l & 7);
        b_base[jj] = brow * ASTRIDE + ((l >> 3) & 1) * 16;
    }

    float acc[4][4][4];
    #pragma unroll
    for (int i = 0; i < 4; i++)
        #pragma unroll
        for (int j = 0; j < 4; j++)
            #pragma unroll
            for (int e = 0; e < 4; e++) acc[i][j][e] = 0.f;

    float4 ax[4];

    auto load_x = [&](int c) {
        const float4* p = reinterpret_cast<const float4*>(px + c * KC);
        #pragma unroll
        for (int j = 0; j < 4; j++) ax[j] = p[j];
    };
    auto load_b = [&](int c, int s) {
        const __nv_bfloat16* src = pw + c * KC;
        uint32_t dst = sb + BB(s) + b_dst;
        CP_ASYNC16(dst,      src);
        CP_ASYNC16(dst + 16, src + 8);
        CP_COMMIT();
    };
    auto store_a = [&](int s) {
        uint32_t h[8], lo[8];
        #pragma unroll
        for (int j = 0; j < 4; j++) {
            float4 v = ax[j];
            __nv_bfloat16 h0 = __float2bfloat16_rn(v.x);
            __nv_bfloat16 h1 = __float2bfloat16_rn(v.y);
            __nv_bfloat16 h2 = __float2bfloat16_rn(v.z);
            __nv_bfloat16 h3 = __float2bfloat16_rn(v.w);
            h[2*j]   = pack_bf16(h0, h1);
            h[2*j+1] = pack_bf16(h2, h3);
            lo[2*j]   = pack_bf16(__float2bfloat16_rn(v.x - __bfloat162float(h0)),
                                  __float2bfloat16_rn(v.y - __bfloat162float(h1)));
            lo[2*j+1] = pack_bf16(__float2bfloat16_rn(v.z - __bfloat162float(h2)),
                                  __float2bfloat16_rn(v.w - __bfloat162float(h3)));
        }
        char* ph = smem + AHI(s) + a_sts;
        char* pl = smem + ALO(s) + a_sts;
        *reinterpret_cast<uint4*>(ph)      = make_uint4(h[0], h[1], h[2], h[3]);
        *reinterpret_cast<uint4*>(ph + 16) = make_uint4(h[4], h[5], h[6], h[7]);
        *reinterpret_cast<uint4*>(pl)      = make_uint4(lo[0], lo[1], lo[2], lo[3]);
        *reinterpret_cast<uint4*>(pl + 16) = make_uint4(lo[4], lo[5], lo[6], lo[7]);
    };
    auto do_mma = [&](int s) {
        #pragma unroll
        for (int ks = 0; ks < KC / 16; ks++) {
            uint32_t b[4][2], a[4][4];
            #pragma unroll
            for (int jj = 0; jj < 2; jj++)
                ldm_x4(b[2*jj][0], b[2*jj][1], b[2*jj+1][0], b[2*jj+1][1],
                       sb + BB(s) + b_base[jj] + ks * 32);
            // hi pass
            #pragma unroll
            for (int i = 0; i < 4; i++)
                ldm_x4(a[i][0], a[i][1], a[i][2], a[i][3],
                       sb + AHI(s) + a_base[i] + ks * 32);
            #pragma unroll
            for (int i = 0; i < 4; i++)
                #pragma unroll
                for (int j = 0; j < 4; j++)
                    mma16816(acc[i][j], a[i], b[j]);
            // lo pass (B frags reused)
            #pragma unroll
            for (int i = 0; i < 4; i++)
                ldm_x4(a[i][0], a[i][1], a[i][2], a[i][3],
                       sb + ALO(s) + a_base[i] + ks * 32);
            #pragma unroll
            for (int i = 0; i < 4; i++)
                #pragma unroll
                for (int j = 0; j < 4; j++)
                    mma16816(acc[i][j], a[i], b[j]);
        }
    };

    // ---- prologue ----
    load_b(0, 0);
    load_x(0);
    store_a(0);
    CP_WAIT0();
    __syncthreads();

    // ---- mainloop: 32 K-chunks, double-buffered, one barrier per chunk ----
    for (int c = 0; c < NCHUNK; c++) {
        int s = c & 1;
        if (c + 1 < NCHUNK) {
            load_b(c + 1, s ^ 1);
            load_x(c + 1);
        }
        do_mma(s);
        if (c + 1 < NCHUNK) store_a(s ^ 1);
        CP_WAIT0();
        __syncthreads();
    }

    // ---- epilogue: scale by 1/127, add bias, float2 stores ----
    const float inv = 1.0f / 127.0f;
    float2 bv[4];
    #pragma unroll
    for (int j = 0; j < 4; j++) {
        int n = wn * 32 + j * 8 + (l & 3) * 2;
        bv[j].x = __ldg(&g_bq[n]);
        bv[j].y = __ldg(&g_bq[n + 1]);
    }
    #pragma unroll
    for (int i = 0; i < 4; i++) {
        int m = m0 + wm * 64 + i * 16 + (l >> 2);
        #pragma unroll
        for (int j = 0; j < 4; j++) {
            int n = wn * 32 + j * 8 + (l & 3) * 2;
            if (m < Mtotal) {
                float2 o0 = make_float2(acc[i][j][0] * inv + bv[j].x,
                                        acc[i][j][1] * inv + bv[j].y);
                *reinterpret_cast<float2*>(out + (size_t)m * D_OUT + n) = o0;
            }
            if (m + 8 < Mtotal) {
                float2 o1 = make_float2(acc[i][j][2] * inv + bv[j].x,
                                        acc[i][j][3] * inv + bv[j].y);
                *reinterpret_cast<float2*>(out + (size_t)(m + 8) * D_OUT + n) = o1;
            }
        }
    }
}

// -------- launch --------
extern "C" void kernel_launch(void* const* d_in, const int* in_sizes, int n_in,
                              void* d_out, int out_size) {
    const float* x = (const float*)d_in[0];
    const float* W = (const float*)d_in[1];
    const float* b = (const float*)d_in[2];
    float* out = (float*)d_out;

    int M = in_sizes[0] / D_IN;

    cudaFuncSetAttribute(pwb_gemm, cudaFuncAttributeMaxDynamicSharedMemorySize, SMEM_TOTAL);

    pwb_prep<<<dim3(D_IN / 32, D_OUT / 32), dim3(32, 32)>>>(W, b);
    pwb_gemm<<<(M + TILE_M - 1) / TILE_M, 256, SMEM_TOTAL>>>(x, out, M);
}

// round 3
// speedup vs baseline: 1.2863x; 1.2863x over previous
#include <cuda_runtime.h>
#include <cuda_fp16.h>
#include <cstdint>

#define D_IN   1024
#define D_OUT  128
#define TILE_M 128
#define KC     32
#define NCHUNK (D_IN / KC)

// -------- persistent scratch (no allocations allowed) --------
__device__ __align__(16) __half g_Wt[D_OUT * D_IN];  // [n][k] = round(clip(W)*127), integer -> exact in fp16
__device__ float g_bq[D_OUT];

// -------- smem layout: rows padded to 80B (conflict-free ldmatrix) --------
#define ASTRIDE 80
#define A_BYTES (128 * ASTRIDE)            // 10240 (128 rows x 32 fp16)
#define STAGE   (2 * A_BYTES)              // A + B = 20480
#define AA(s)   ((s) * STAGE)
#define BB(s)   (AA(s) + A_BYTES)
#define SMEM_TOTAL (2 * STAGE)             // 40960 -> 2 CTAs/SM (reg-bound anyway)

// -------- PTX helpers --------
__device__ __forceinline__ uint32_t smem_u32(const void* p) {
    uint32_t a;
    asm("{ .reg .u64 t; cvta.to.shared.u64 t, %1; cvt.u32.u64 %0, t; }" : "=r"(a) : "l"(p));
    return a;
}
#define CP_ASYNC16(dst, src) \
    asm volatile("cp.async.cg.shared.global [%0], [%1], 16;" :: "r"(dst), "l"(src) : "memory")
#define CP_COMMIT()  asm volatile("cp.async.commit_group;" ::: "memory")
#define CP_WAIT0()   asm volatile("cp.async.wait_group 0;" ::: "memory")

__device__ __forceinline__ void ldm_x4(uint32_t& r0, uint32_t& r1, uint32_t& r2, uint32_t& r3,
                                       uint32_t addr) {
    asm volatile("ldmatrix.sync.aligned.m8n8.x4.shared.b16 {%0,%1,%2,%3}, [%4];"
                 : "=r"(r0), "=r"(r1), "=r"(r2), "=r"(r3) : "r"(addr));
}
__device__ __forceinline__ void mma16816(float* c, const uint32_t* a, const uint32_t* b) {
    asm volatile("mma.sync.aligned.m16n8k16.row.col.f32.f16.f16.f32 "
                 "{%0,%1,%2,%3}, {%4,%5,%6,%7}, {%8,%9}, {%0,%1,%2,%3};"
                 : "+f"(c[0]), "+f"(c[1]), "+f"(c[2]), "+f"(c[3])
                 : "r"(a[0]), "r"(a[1]), "r"(a[2]), "r"(a[3]), "r"(b[0]), "r"(b[1]));
}
__device__ __forceinline__ uint32_t pack_h2(__half a, __half b) {
    __half2 t(a, b);
    return *reinterpret_cast<uint32_t*>(&t);
}

// -------- prep: quantize + transpose W (coalesced both sides), quantize b --------
__global__ void pwb_prep(const float* __restrict__ W, const float* __restrict__ b) {
    __shared__ float t[32][33];
    int tx = threadIdx.x, ty = threadIdx.y;
    int k0 = blockIdx.x * 32, n0 = blockIdx.y * 32;
    float w = W[(size_t)(k0 + ty) * D_OUT + n0 + tx];
    t[ty][tx] = rintf(fminf(fmaxf(w, -1.f), 1.f) * 127.f);   // integer, exact in fp16
    __syncthreads();
    g_Wt[(size_t)(n0 + ty) * D_IN + k0 + tx] = __float2half_rn(t[tx][ty]);
    if (blockIdx.x == 0 && blockIdx.y == 0) {
        int tid = ty * 32 + tx;
        if (tid < D_OUT)
            g_bq[tid] = rintf(fminf(fmaxf(b[tid], -1.f), 1.f) * 127.f) * (1.0f / 127.0f);
    }
}

// -------- main GEMM: single-pass fp16 x, exact-fp16 integer W, fp32 accumulate --------
__global__ void __launch_bounds__(256, 2)
pwb_gemm(const float* __restrict__ x, float* __restrict__ out, int Mtotal) {
    extern __shared__ char smem[];
    uint32_t sb = smem_u32(smem);
    int tid = threadIdx.x;
    int m0 = blockIdx.x * TILE_M;

    int l  = tid & 31;
    int w  = tid >> 5;
    int wm = w & 1;          // 2 warp-rows of 64
    int wn = w >> 1;         // 4 warp-cols of 32

    // ---- loader mapping: 2 threads per row, 16 elements each ----
    int r    = tid >> 1;
    int half = tid & 1;
    const float* px = x + (size_t)(m0 + r) * D_IN + half * 16;
    const __half* pw = reinterpret_cast<const __half*>(g_Wt) + (size_t)r * D_IN + half * 16;
    uint32_t a_sts = r * ASTRIDE + half * 32;
    uint32_t b_dst = r * ASTRIDE + half * 32;

    // ---- ldmatrix lane address bases ----
    uint32_t a_base[4], b_base[2];
    #pragma unroll
    for (int i = 0; i < 4; i++) {
        int arow = wm * 64 + i * 16 + (l & 15);
        a_base[i] = arow * ASTRIDE + (l >> 4) * 16;
    }
    #pragma unroll
    for (int jj = 0; jj < 2; jj++) {
        int brow = wn * 32 + jj * 16 + ((l >> 4) & 1) * 8 + (l & 7);
        b_base[jj] = brow * ASTRIDE + ((l >> 3) & 1) * 16;
    }

    float acc[4][4][4];
    #pragma unroll
    for (int i = 0; i < 4; i++)
        #pragma unroll
        for (int j = 0; j < 4; j++)
            #pragma unroll
            for (int e = 0; e < 4; e++) acc[i][j][e] = 0.f;

    float4 ax[4];

    auto load_x = [&](int c) {
        const float4* p = reinterpret_cast<const float4*>(px + c * KC);
        #pragma unroll
        for (int j = 0; j < 4; j++) ax[j] = p[j];
    };
    auto load_b = [&](int c, int s) {
        const __half* src = pw + c * KC;
        uint32_t dst = sb + BB(s) + b_dst;
        CP_ASYNC16(dst,      src);
        CP_ASYNC16(dst + 16, src + 8);
        CP_COMMIT();
    };
    auto store_a = [&](int s) {
        uint32_t h[8];
        #pragma unroll
        for (int j = 0; j < 4; j++) {
            float4 v = ax[j];
            h[2*j]   = pack_h2(__float2half_rn(v.x), __float2half_rn(v.y));
            h[2*j+1] = pack_h2(__float2half_rn(v.z), __float2half_rn(v.w));
        }
        char* ph = smem + AA(s) + a_sts;
        *reinterpret_cast<uint4*>(ph)      = make_uint4(h[0], h[1], h[2], h[3]);
        *reinterpret_cast<uint4*>(ph + 16) = make_uint4(h[4], h[5], h[6], h[7]);
    };
    auto do_mma = [&](int s) {
        #pragma unroll
        for (int ks = 0; ks < KC / 16; ks++) {
            uint32_t b[4][2], a[4][4];
            #pragma unroll
            for (int jj = 0; jj < 2; jj++)
                ldm_x4(b[2*jj][0], b[2*jj][1], b[2*jj+1][0], b[2*jj+1][1],
                       sb + BB(s) + b_base[jj] + ks * 32);
            #pragma unroll
            for (int i = 0; i < 4; i++)
                ldm_x4(a[i][0], a[i][1], a[i][2], a[i][3],
                       sb + AA(s) + a_base[i] + ks * 32);
            #pragma unroll
            for (int i = 0; i < 4; i++)
                #pragma unroll
                for (int j = 0; j < 4; j++)
                    mma16816(acc[i][j], a[i], b[j]);
        }
    };

    // ---- prologue ----
    load_b(0, 0);
    load_x(0);
    store_a(0);
    CP_WAIT0();
    __syncthreads();

    // ---- mainloop: 32 K-chunks, double-buffered, one barrier per chunk ----
    for (int c = 0; c < NCHUNK; c++) {
        int s = c & 1;
        if (c + 1 < NCHUNK) {
            load_b(c + 1, s ^ 1);
            load_x(c + 1);
        }
        do_mma(s);
        if (c + 1 < NCHUNK) store_a(s ^ 1);
        CP_WAIT0();
        __syncthreads();
    }

    // ---- epilogue: scale by 1/127, add bias, float2 stores ----
    const float inv = 1.0f / 127.0f;
    float2 bv[4];
    #pragma unroll
    for (int j = 0; j < 4; j++) {
        int n = wn * 32 + j * 8 + (l & 3) * 2;
        bv[j].x = __ldg(&g_bq[n]);
        bv[j].y = __ldg(&g_bq[n + 1]);
    }
    #pragma unroll
    for (int i = 0; i < 4; i++) {
        int m = m0 + wm * 64 + i * 16 + (l >> 2);
        #pragma unroll
        for (int j = 0; j < 4; j++) {
            int n = wn * 32 + j * 8 + (l & 3) * 2;
            if (m < Mtotal) {
                float2 o0 = make_float2(acc[i][j][0] * inv + bv[j].x,
                                        acc[i][j][1] * inv + bv[j].y);
                *reinterpret_cast<float2*>(out + (size_t)m * D_OUT + n) = o0;
            }
            if (m + 8 < Mtotal) {
                float2 o1 = make_float2(acc[i][j][2] * inv + bv[j].x,
                                        acc[i][j][3] * inv + bv[j].y);
                *reinterpret_cast<float2*>(out + (size_t)(m + 8) * D_OUT + n) = o1;
            }
        }
    }
}

// -------- launch --------
extern "C" void kernel_launch(void* const* d_in, const int* in_sizes, int n_in,
                              void* d_out, int out_size) {
    const float* x = (const float*)d_in[0];
    const float* W = (const float*)d_in[1];
    const float* b = (const float*)d_in[2];
    float* out = (float*)d_out;

    int M = in_sizes[0] / D_IN;

    cudaFuncSetAttribute(pwb_gemm, cudaFuncAttributeMaxDynamicSharedMemorySize, SMEM_TOTAL);

    pwb_prep<<<dim3(D_IN / 32, D_OUT / 32), dim3(32, 32)>>>(W, b);
    pwb_gemm<<<(M + TILE_M - 1) / TILE_M, 256, SMEM_TOTAL>>>(x, out, M);
}